// round 12
// baseline (speedup 1.0000x reference)
#include <cuda_runtime.h>
#include <cuda_bf16.h>
#include <math.h>
#include <stdint.h>

#define BB 2
#define C 128
#define H 192
#define W 192
#define HW (H*W)
#define CHW (C*HW)
#define E 128
#define SWID 24
#define NN 576
#define BF 128
#define NB 256

// ---------------- mma helpers (base PTX, compute_103-safe) ----------------
__device__ __forceinline__ uint32_t s2u(const void* p){
  uint32_t a;
  asm("{ .reg .u64 t; cvta.to.shared.u64 t, %1; cvt.u32.u64 %0, t; }" : "=r"(a) : "l"(p));
  return a;
}
__device__ __forceinline__ void cp16(uint32_t d, const void* g){
  asm volatile("cp.async.cg.shared.global [%0], [%1], 16;" :: "r"(d), "l"(g));
}
__device__ __forceinline__ void cp16z(uint32_t d, const void* g, bool pred){
  int sz = pred ? 16 : 0;
  asm volatile("cp.async.cg.shared.global [%0], [%1], 16, %2;" :: "r"(d), "l"(g), "r"(sz));
}
#define CP_COMMIT() asm volatile("cp.async.commit_group;" ::: "memory")

__device__ __forceinline__ void ldsm4(uint32_t* r, uint32_t addr){
  asm volatile("ldmatrix.sync.aligned.m8n8.x4.shared.b16 {%0,%1,%2,%3}, [%4];"
    : "=r"(r[0]),"=r"(r[1]),"=r"(r[2]),"=r"(r[3]) : "r"(addr));
}
__device__ __forceinline__ void mma_bf16(float* c, const uint32_t* a, uint32_t b0, uint32_t b1){
  asm volatile("mma.sync.aligned.m16n8k16.row.col.f32.bf16.bf16.f32 "
    "{%0,%1,%2,%3}, {%4,%5,%6,%7}, {%8,%9}, {%0,%1,%2,%3};"
    : "+f"(c[0]),"+f"(c[1]),"+f"(c[2]),"+f"(c[3])
    : "r"(a[0]),"r"(a[1]),"r"(a[2]),"r"(a[3]), "r"(b0),"r"(b1));
}
__device__ __forceinline__ void mma_tf32(float* c, uint32_t a0, uint32_t a1, uint32_t a2,
                                         uint32_t a3, uint32_t b0, uint32_t b1){
  asm volatile("mma.sync.aligned.m16n8k8.row.col.f32.tf32.tf32.f32 "
    "{%0,%1,%2,%3}, {%4,%5,%6,%7}, {%8,%9}, {%0,%1,%2,%3};"
    : "+f"(c[0]),"+f"(c[1]),"+f"(c[2]),"+f"(c[3])
    : "r"(a0),"r"(a1),"r"(a2),"r"(a3), "r"(b0),"r"(b1));
}
__device__ __forceinline__ void mma_tf32_f4(float* cA, float* cB, uint32_t a0, uint32_t a1,
                                            uint32_t a2, uint32_t a3, float4 bv){
  mma_tf32(cA, a0, a1, a2, a3, __float_as_uint(bv.x), __float_as_uint(bv.y));
  mma_tf32(cB, a0, a1, a2, a3, __float_as_uint(bv.z), __float_as_uint(bv.w));
}
__device__ __forceinline__ uint32_t packbf(float lo, float hi){
  uint32_t d; asm("cvt.rn.bf16x2.f32 %0, %1, %2;" : "=r"(d) : "f"(hi), "f"(lo)); return d;
}
__device__ __forceinline__ float tf32r(float v){
  uint32_t o; asm("cvt.rna.tf32.f32 %0, %1;" : "=r"(o) : "f"(v));
  return __uint_as_float(o);
}
__device__ __forceinline__ uint32_t ldss(uint32_t a){
  uint32_t v; asm volatile("ld.shared.b32 %0, [%1];" : "=r"(v) : "r"(a)); return v;
}

// ---------------- scratch (static device globals; no allocation) ----------------
__device__ float g_part[BB*NB*2];
__device__ float g_mv[4];
__device__ __nv_bfloat16 g_qkh[(size_t)BF*NN*E];   // [bf][n][e] unit-norm rows
__device__ __nv_bfloat16 g_vh [(size_t)BF*NN*C];   // [bf][c][n]
__device__ float g_y [(size_t)BB*CHW];             // pre-rounded tf32
__device__ float g_h1[(size_t)BB*CHW];             // pre-rounded tf32
__device__ float g_h2[(size_t)BB*CHW];             // pre-rounded tf32
__device__ float4 g_wq1[36864];   // conv1 [kk*16+ci8][jp][lane] paired n8 frags
__device__ float4 g_wq2[36864];   // conv2
__device__ float4 g_wq3[4096];    // 1x1  [ci8][jp][lane]
__device__ float4 g_wq4[4096];    // wqk  [k8*2+eh][jp][lane]

// ---------------- LayerNorm stats ----------------
__global__ void ln_partial_kernel(const float* __restrict__ x){
  int b = blockIdx.y;
  const float* xb = x + (size_t)b*CHW;
  float s = 0.f, ss = 0.f;
  for (int i = blockIdx.x*256 + threadIdx.x; i < CHW; i += NB*256){
    float v = xb[i]; s += v; ss += v*v;
  }
  #pragma unroll
  for (int o = 16; o; o >>= 1){
    s  += __shfl_xor_sync(0xffffffffu, s,  o);
    ss += __shfl_xor_sync(0xffffffffu, ss, o);
  }
  __shared__ float rs[8], rss[8];
  int warp = threadIdx.x >> 5, lane = threadIdx.x & 31;
  if (!lane){ rs[warp] = s; rss[warp] = ss; }
  __syncthreads();
  if (!threadIdx.x){
    float a = 0.f, c2 = 0.f;
    #pragma unroll
    for (int i = 0; i < 8; i++){ a += rs[i]; c2 += rss[i]; }
    g_part[(b*NB + blockIdx.x)*2]   = a;
    g_part[(b*NB + blockIdx.x)*2+1] = c2;
  }
}

__global__ void ln_final_kernel(){
  int b = blockIdx.x, t = threadIdx.x;
  float s  = g_part[(b*NB + t)*2];
  float ss = g_part[(b*NB + t)*2+1];
  #pragma unroll
  for (int o = 16; o; o >>= 1){
    s  += __shfl_xor_sync(0xffffffffu, s,  o);
    ss += __shfl_xor_sync(0xffffffffu, ss, o);
  }
  __shared__ float rs[8], rss[8];
  int warp = t >> 5, lane = t & 31;
  if (!lane){ rs[warp] = s; rss[warp] = ss; }
  __syncthreads();
  if (!t){
    float a = 0.f, c2 = 0.f;
    #pragma unroll
    for (int i = 0; i < 8; i++){ a += rs[i]; c2 += rss[i]; }
    float mean = a / (float)CHW;
    float var  = c2 / (float)CHW - mean*mean;
    g_mv[b*2]   = mean;
    g_mv[b*2+1] = rsqrtf(var + 1e-5f);
  }
}

// ---------------- weight prepack: paired-fragment float4, tf32-rounded ----------------
__global__ void prepack_kernel(const float* __restrict__ w1, const float* __restrict__ w2,
                               const float* __restrict__ w3, const float* __restrict__ wqk){
  int i = blockIdx.x*256 + threadIdx.x;
  if (i < 2*36864){
    const float* w = (i < 36864) ? w1 : w2;
    float4* dst = (i < 36864) ? g_wq1 : g_wq2;
    int j = (i < 36864) ? i : i - 36864;
    int lane = j & 31, jp = (j >> 5) & 7, kidx = j >> 8;
    int kk = kidx >> 4, ci8 = kidx & 15;
    int t = lane & 3, g = lane >> 2;
    int ci = ci8*8 + t;
    int coA = (2*jp)*8 + g, coB = (2*jp+1)*8 + g;
    dst[j] = make_float4(tf32r(w[(coA*128 + ci)*9 + kk]),
                         tf32r(w[(coA*128 + ci + 4)*9 + kk]),
                         tf32r(w[(coB*128 + ci)*9 + kk]),
                         tf32r(w[(coB*128 + ci + 4)*9 + kk]));
  } else if (i < 2*36864 + 4096){
    int j = i - 2*36864;
    int lane = j & 31, jp = (j >> 5) & 7, ci8 = j >> 8;
    int t = lane & 3, g = lane >> 2;
    int coA = (2*jp)*8 + g, coB = (2*jp+1)*8 + g;
    g_wq3[j] = make_float4(tf32r(w3[coA*128 + ci8*8 + t]),
                           tf32r(w3[coA*128 + ci8*8 + t + 4]),
                           tf32r(w3[coB*128 + ci8*8 + t]),
                           tf32r(w3[coB*128 + ci8*8 + t + 4]));
  } else {
    int j = i - 2*36864 - 4096;
    if (j < 4096){
      int lane = j & 31, jp = (j >> 5) & 3, e2 = (j >> 7) & 1, k8 = j >> 8;
      int t = lane & 3, g = lane >> 2;
      int n8a = e2*8 + 2*jp, n8b = n8a + 1;
      g_wq4[j] = make_float4(tf32r(wqk[(k8*8 + t)*E     + n8a*8 + g]),
                             tf32r(wqk[(k8*8 + t + 4)*E + n8a*8 + g]),
                             tf32r(wqk[(k8*8 + t)*E     + n8b*8 + g]),
                             tf32r(wqk[(k8*8 + t + 4)*E + n8b*8 + g]));
    }
  }
}

// ---------------- prep: unshuffle + tf32-mma qk projection + row L2-norm ----------------
#define PREPM_SMEM (36864 + 512)
__global__ __launch_bounds__(256) void prep_mma_kernel(const float* __restrict__ x){
  int blk = blockIdx.x;
  int r0  = blk*64;
  int bf  = r0 / NN;
  int b   = bf >> 6, k = bf & 63, dy = k >> 3, dx = k & 7;
  float mean = g_mv[b*2], rstd = g_mv[b*2+1];
  extern __shared__ float sm[];
  float* xs  = sm;                 // [c][72]
  float* ssq = sm + 9216;          // [64][2]
  int tid = threadIdx.x;
  int lane = tid & 31, wm = tid >> 5;
  int t = lane & 3, g = lane >> 2;
  uint32_t sb = s2u(sm);

  int n0 = r0 - bf*NN;
  for (int l = tid; l < 8192; l += 256){
    int c = l >> 6, i = l & 63;
    int n  = n0 + i;
    int sh = n / SWID, swp = n - sh*SWID;
    int h  = sh*8 + dy, w = swp*8 + dx;
    float xv = x[(size_t)(b*C + c)*HW + h*W + w];
    g_vh[((size_t)bf*C + c)*NN + n] = __float2bfloat16(xv);
    xs[c*72 + i] = tf32r((xv - mean)*rstd);
  }
  __syncthreads();

  int rg = wm & 3, eh = wm >> 2;
  float acc[8][4] = {};
  #pragma unroll
  for (int k8 = 0; k8 < 16; k8++){
    uint32_t ab = sb + (uint32_t)(((k8*8 + t)*72 + rg*16 + g)*4);
    uint32_t a0 = ldss(ab);
    uint32_t a1 = ldss(ab + 32);
    uint32_t a2 = ldss(ab + 4*72*4);
    uint32_t a3 = ldss(ab + 4*72*4 + 32);
    const float4* wrow = g_wq4 + (size_t)((k8*2 + eh)*4)*32 + lane;
    #pragma unroll
    for (int jp = 0; jp < 4; jp++){
      float4 bv = __ldg(wrow + jp*32);
      mma_tf32_f4(acc[2*jp], acc[2*jp+1], a0, a1, a2, a3, bv);
    }
  }

  float s0 = 0.f, s1 = 0.f;
  #pragma unroll
  for (int j = 0; j < 8; j++){
    s0 += acc[j][0]*acc[j][0] + acc[j][1]*acc[j][1];
    s1 += acc[j][2]*acc[j][2] + acc[j][3]*acc[j][3];
  }
  s0 += __shfl_xor_sync(0xffffffffu, s0, 1);
  s0 += __shfl_xor_sync(0xffffffffu, s0, 2);
  s1 += __shfl_xor_sync(0xffffffffu, s1, 1);
  s1 += __shfl_xor_sync(0xffffffffu, s1, 2);
  if (t == 0){
    ssq[(rg*16 + g)*2 + eh]     = s0;
    ssq[(rg*16 + g + 8)*2 + eh] = s1;
  }
  __syncthreads();
  int row0 = rg*16 + g, row1 = row0 + 8;
  float inv0 = 1.f/(sqrtf(ssq[row0*2] + ssq[row0*2+1]) + 1e-8f);
  float inv1 = 1.f/(sqrtf(ssq[row1*2] + ssq[row1*2+1]) + 1e-8f);

  __nv_bfloat16* q0 = g_qkh + (size_t)(r0 + row0)*E + eh*64 + 2*t;
  __nv_bfloat16* q1 = g_qkh + (size_t)(r0 + row1)*E + eh*64 + 2*t;
  #pragma unroll
  for (int j = 0; j < 8; j++){
    *(uint32_t*)(q0 + j*8) = packbf(acc[j][0]*inv0, acc[j][1]*inv0);
    *(uint32_t*)(q1 + j*8) = packbf(acc[j][2]*inv1, acc[j][3]*inv1);
  }
}

// ---------------- attention: mma.sync bf16 flash, single-V-buffer ----------------
#define AOFF_Q  0
#define AOFF_K0 16384
#define AOFF_K1 32768
#define AOFF_V  49152
#define ATTN_SMEM 65536

__device__ __forceinline__ void load_k(uint32_t sb, const __nv_bfloat16* qsrc, int jt, int tid){
  uint32_t kb = sb + ((jt & 1) ? AOFF_K1 : AOFF_K0);
  const __nv_bfloat16* ks = qsrc + (size_t)jt*64*E;
  #pragma unroll
  for (int r = 0; r < 8; r++){
    int idx = tid + 128*r;
    int row = idx >> 4, ch = idx & 15;
    cp16(kb + row*256 + ((ch ^ (row & 7))*16), ks + (size_t)row*E + ch*8);
  }
  CP_COMMIT();
}
__device__ __forceinline__ void load_v(uint32_t sb, const __nv_bfloat16* vsrc, int jt, int tid){
  uint32_t vb = sb + AOFF_V;
  const __nv_bfloat16* vs = vsrc + jt*64;
  #pragma unroll
  for (int r = 0; r < 8; r++){
    int idx = tid + 128*r;
    int row = idx >> 3, ch = idx & 7;
    cp16(vb + row*128 + ((ch ^ (row & 7))*16), vs + (size_t)row*NN + ch*8);
  }
  CP_COMMIT();
}

__global__ __launch_bounds__(128) void attn_mma_kernel(const float* __restrict__ x){
  extern __shared__ char smc[];
  const int tid = threadIdx.x;
  const int lane = tid & 31, w = tid >> 5;
  const int rt = blockIdx.x, bf = blockIdx.y;
  const int r0 = rt*64;
  const __nv_bfloat16* qsrc = g_qkh + (size_t)bf*NN*E;
  const __nv_bfloat16* vsrc = g_vh  + (size_t)bf*C*NN;
  uint32_t sb = s2u(smc);

  {
    const __nv_bfloat16* qs = qsrc + (size_t)r0*E;
    #pragma unroll
    for (int r = 0; r < 8; r++){
      int idx = tid + 128*r;
      int row = idx >> 4, ch = idx & 15;
      cp16(sb + AOFF_Q + row*256 + ((ch ^ (row & 7))*16), qs + (size_t)row*E + ch*8);
    }
    CP_COMMIT();
  }
  load_k(sb, qsrc, 0, tid);
  asm volatile("cp.async.wait_group 0;" ::: "memory");
  __syncthreads();

  uint32_t qa[8][4];
  #pragma unroll
  for (int kk = 0; kk < 8; kk++){
    int row = w*16 + (lane & 15);
    int ch  = kk*2 + (lane >> 4);
    ldsm4(qa[kk], sb + AOFF_Q + row*256 + ((ch ^ (row & 7))*16));
  }

  float oacc[16][4];
  #pragma unroll
  for (int i = 0; i < 16; i++){ oacc[i][0]=0.f; oacc[i][1]=0.f; oacc[i][2]=0.f; oacc[i][3]=0.f; }
  float rsum0 = 0.f, rsum1 = 0.f;
  const float invsE = 0.08838834764831845f;

  for (int jt = 0; jt < 9; jt++){
    __syncthreads();
    if (jt < 8) load_k(sb, qsrc, jt+1, tid);
    load_v(sb, vsrc, jt, tid);
    if (jt < 8) asm volatile("cp.async.wait_group 2;" ::: "memory");
    else        asm volatile("cp.async.wait_group 1;" ::: "memory");
    __syncthreads();

    uint32_t kbase = sb + ((jt & 1) ? AOFF_K1 : AOFF_K0);

    float sc[8][4];
    #pragma unroll
    for (int i = 0; i < 8; i++){ sc[i][0]=0.f; sc[i][1]=0.f; sc[i][2]=0.f; sc[i][3]=0.f; }
    #pragma unroll
    for (int jp = 0; jp < 4; jp++){
      #pragma unroll
      for (int kk = 0; kk < 8; kk++){
        uint32_t kb[4];
        int row = jp*16 + (lane & 15);
        int ch  = kk*2 + (lane >> 4);
        ldsm4(kb, kbase + row*256 + ((ch ^ (row & 7))*16));
        mma_bf16(sc[2*jp],   qa[kk], kb[0], kb[2]);
        mma_bf16(sc[2*jp+1], qa[kk], kb[1], kb[3]);
      }
    }

    if (jt < 8) asm volatile("cp.async.wait_group 1;" ::: "memory");
    else        asm volatile("cp.async.wait_group 0;" ::: "memory");
    __syncthreads();

    uint32_t pa[4][4];
    #pragma unroll
    for (int j = 0; j < 8; j++){
      float p0 = __expf(sc[j][0]*invsE), p1 = __expf(sc[j][1]*invsE);
      float p2 = __expf(sc[j][2]*invsE), p3 = __expf(sc[j][3]*invsE);
      rsum0 += p0 + p1; rsum1 += p2 + p3;
      int kk = j >> 1;
      if ((j & 1) == 0){ pa[kk][0] = packbf(p0,p1); pa[kk][1] = packbf(p2,p3); }
      else             { pa[kk][2] = packbf(p0,p1); pa[kk][3] = packbf(p2,p3); }
    }

    #pragma unroll
    for (int jnp = 0; jnp < 8; jnp++){
      #pragma unroll
      for (int kk = 0; kk < 4; kk++){
        uint32_t vb[4];
        int row = jnp*16 + (lane & 15);
        int ch  = kk*2 + (lane >> 4);
        ldsm4(vb, sb + AOFF_V + row*128 + ((ch ^ (row & 7))*16));
        mma_bf16(oacc[2*jnp],   pa[kk], vb[0], vb[2]);
        mma_bf16(oacc[2*jnp+1], pa[kk], vb[1], vb[3]);
      }
    }
  }

  rsum0 += __shfl_xor_sync(0xffffffffu, rsum0, 1);
  rsum0 += __shfl_xor_sync(0xffffffffu, rsum0, 2);
  rsum1 += __shfl_xor_sync(0xffffffffu, rsum1, 1);
  rsum1 += __shfl_xor_sync(0xffffffffu, rsum1, 2);
  float inv0 = 1.f/rsum0, inv1 = 1.f/rsum1;

  // residual + shuffle back, written PRE-ROUNDED tf32 (conv1 consumes g_y raw)
  int g = lane >> 2, t4 = lane & 3;
  int b = bf >> 6, kk2 = bf & 63, dy = kk2 >> 3, dx = kk2 & 7;
  int nA = r0 + w*16 + g;
  int nB = nA + 8;
  int shA = nA / SWID, swA = nA - shA*SWID;
  int shB = nB / SWID, swB = nB - shB*SWID;
  size_t baseA = (size_t)b*CHW + (size_t)(shA*8 + dy)*W + (swA*8 + dx);
  size_t baseB = (size_t)b*CHW + (size_t)(shB*8 + dy)*W + (swB*8 + dx);
  #pragma unroll
  for (int jn = 0; jn < 16; jn++){
    int c0 = jn*8 + 2*t4;
    size_t giA = baseA + (size_t)c0*HW;
    size_t giB = baseB + (size_t)c0*HW;
    g_y[giA]    = tf32r(x[giA]    + oacc[jn][0]*inv0);
    g_y[giA+HW] = tf32r(x[giA+HW] + oacc[jn][1]*inv0);
    g_y[giB]    = tf32r(x[giB]    + oacc[jn][2]*inv1);
    g_y[giB+HW] = tf32r(x[giB+HW] + oacc[jn][3]*inv1);
  }
}

// ---------------- 3x3 dilated conv via tf32 mma, cp.async SINGLE-buffer staging ----------------
// input pre-rounded tf32. smem: [32 ci][12 rows][24 cols] pitch 296 floats/ci = 37888 B
#define C3_SMEM 37888
__global__ __launch_bounds__(256) void conv3_mma_kernel(const float* __restrict__ in,
                                                        const float4* __restrict__ wp,
                                                        const float* __restrict__ bias,
                                                        float* __restrict__ out,
                                                        int do_round){
  int txle = blockIdx.x*16, tyle = blockIdx.y*8, b = blockIdx.z;
  extern __shared__ float sm[];
  int tid = threadIdx.x, lane = tid & 31, wm = tid >> 5;
  int t = lane & 3, g = lane >> 2;
  uint32_t sb = s2u(sm);
  float acc[16][4] = {};

  for (int chunk = 0; chunk < 4; chunk++){
    __syncthreads();
    #pragma unroll
    for (int r = 0; r < 9; r++){
      int idx = tid + 256*r;                 // 0..2303 = 32ci * 72 16B-chunks
      int ci  = idx / 72;
      int rem = idx - ci*72;
      int row = rem / 6, seg = rem - row*6;
      int gy = tyle + row - 2, gx = txle + seg*4 - 4;
      bool ok = (gy >= 0) & (gy < H) & (gx >= 0) & (gx < W);
      const float* src = ok ? in + (size_t)(b*C + chunk*32 + ci)*HW + gy*W + gx : in;
      cp16z(sb + (uint32_t)(ci*1184 + row*96 + seg*16), src, ok);
    }
    CP_COMMIT();
    asm volatile("cp.async.wait_group 0;" ::: "memory");
    __syncthreads();

    #pragma unroll
    for (int kk = 0; kk < 9; kk++){
      int ky = kk/3, kx = kk - ky*3;
      #pragma unroll
      for (int c8 = 0; c8 < 4; c8++){
        uint32_t ab = sb + (uint32_t)((c8*8 + t)*1184 + (wm + 2*ky)*96 + (g + 2*kx + 2)*4);
        uint32_t a0 = ldss(ab);
        uint32_t a1 = ldss(ab + 32);           // px +8
        uint32_t a2 = ldss(ab + 4*1184);       // ci +4
        uint32_t a3 = ldss(ab + 4*1184 + 32);
        const float4* wrow = wp + (size_t)((kk*16 + chunk*4 + c8)*8)*32 + lane;
        #pragma unroll
        for (int jp = 0; jp < 8; jp++){
          float4 bv = __ldg(wrow + jp*32);
          mma_tf32_f4(acc[2*jp], acc[2*jp+1], a0, a1, a2, a3, bv);
        }
      }
    }
  }

  int gx0 = txle + g, gy = tyle + wm;
  if (do_round){
    #pragma unroll
    for (int j = 0; j < 16; j++){
      int co = j*8 + 2*t;
      float2 bb = *(const float2*)&bias[co];
      size_t o0 = (size_t)(b*C + co)*HW + (size_t)gy*W + gx0;
      out[o0]        = tf32r(fmaxf(acc[j][0] + bb.x, 0.f));
      out[o0 + HW]   = tf32r(fmaxf(acc[j][1] + bb.y, 0.f));
      out[o0 + 8]    = tf32r(fmaxf(acc[j][2] + bb.x, 0.f));
      out[o0 + HW+8] = tf32r(fmaxf(acc[j][3] + bb.y, 0.f));
    }
  } else {
    #pragma unroll
    for (int j = 0; j < 16; j++){
      int co = j*8 + 2*t;
      float2 bb = *(const float2*)&bias[co];
      size_t o0 = (size_t)(b*C + co)*HW + (size_t)gy*W + gx0;
      out[o0]        = fmaxf(acc[j][0] + bb.x, 0.f);
      out[o0 + HW]   = fmaxf(acc[j][1] + bb.y, 0.f);
      out[o0 + 8]    = fmaxf(acc[j][2] + bb.x, 0.f);
      out[o0 + HW+8] = fmaxf(acc[j][3] + bb.y, 0.f);
    }
  }
}

// ---------------- 1x1 conv via tf32 mma + bias + residual, cp.async single-buffer ----------------
// input pre-rounded tf32. smem: [32 ci][136] = 17408 B
#define C1M_SMEM 17408
__global__ __launch_bounds__(256) void conv1x1_mma_kernel(const float* __restrict__ hin,
                                                          const float4* __restrict__ wp,
                                                          const float* __restrict__ bias,
                                                          const float* __restrict__ x,
                                                          float* __restrict__ out){
  int blk = blockIdx.x;
  int b = blk / 288, hw0 = (blk - b*288)*128;
  extern __shared__ float sm[];
  int tid = threadIdx.x, lane = tid & 31, wm = tid >> 5;
  int t = lane & 3, g = lane >> 2;
  uint32_t sb = s2u(sm);
  float acc[16][4] = {};

  for (int chunk = 0; chunk < 4; chunk++){
    __syncthreads();
    #pragma unroll
    for (int r = 0; r < 4; r++){
      int idx = tid + 256*r;                // 0..1023
      int ci = idx >> 5, seg = idx & 31;
      cp16(sb + (uint32_t)(ci*544 + seg*16),
           hin + (size_t)(b*C + chunk*32 + ci)*HW + hw0 + seg*4);
    }
    CP_COMMIT();
    asm volatile("cp.async.wait_group 0;" ::: "memory");
    __syncthreads();

    #pragma unroll
    for (int c8 = 0; c8 < 4; c8++){
      uint32_t ab = sb + (uint32_t)(((c8*8 + t)*136 + wm*16 + g)*4);
      uint32_t a0 = ldss(ab);
      uint32_t a1 = ldss(ab + 32);
      uint32_t a2 = ldss(ab + 4*136*4);
      uint32_t a3 = ldss(ab + 4*136*4 + 32);
      const float4* wrow = wp + (size_t)((chunk*4 + c8)*8)*32 + lane;
      #pragma unroll
      for (int jp = 0; jp < 8; jp++){
        float4 bv = __ldg(wrow + jp*32);
        mma_tf32_f4(acc[2*jp], acc[2*jp+1], a0, a1, a2, a3, bv);
      }
    }
  }

  int p0 = hw0 + wm*16 + g;
  #pragma unroll
  for (int j = 0; j < 16; j++){
    int co = j*8 + 2*t;
    float2 bb = *(const float2*)&bias[co];
    size_t o0 = (size_t)(b*C + co)*HW + p0;
    out[o0]        = x[o0]        + acc[j][0] + bb.x;
    out[o0 + HW]   = x[o0 + HW]   + acc[j][1] + bb.y;
    out[o0 + 8]    = x[o0 + 8]    + acc[j][2] + bb.x;
    out[o0 + HW+8] = x[o0 + HW+8] + acc[j][3] + bb.y;
  }
}

// ---------------- launch ----------------
extern "C" void kernel_launch(void* const* d_in, const int* in_sizes, int n_in,
                              void* d_out, int out_size){
  const float* x   = (const float*)d_in[0];
  const float* wqk = (const float*)d_in[1];
  const float* w1  = (const float*)d_in[2];
  const float* b1  = (const float*)d_in[3];
  const float* w2  = (const float*)d_in[4];
  const float* b2  = (const float*)d_in[5];
  const float* w3  = (const float*)d_in[6];
  const float* b3  = (const float*)d_in[7];
  float* out = (float*)d_out;

  cudaFuncSetAttribute(prep_mma_kernel,   cudaFuncAttributeMaxDynamicSharedMemorySize, PREPM_SMEM);
  cudaFuncSetAttribute(attn_mma_kernel,   cudaFuncAttributeMaxDynamicSharedMemorySize, ATTN_SMEM);
  cudaFuncSetAttribute(conv3_mma_kernel,  cudaFuncAttributeMaxDynamicSharedMemorySize, C3_SMEM);
  cudaFuncSetAttribute(conv1x1_mma_kernel,cudaFuncAttributeMaxDynamicSharedMemorySize, C1M_SMEM);

  void *py_, *ph1_, *ph2_, *pw1_, *pw2_, *pw3_;
  cudaGetSymbolAddress(&py_,  g_y);
  cudaGetSymbolAddress(&ph1_, g_h1);
  cudaGetSymbolAddress(&ph2_, g_h2);
  cudaGetSymbolAddress(&pw1_, g_wq1);
  cudaGetSymbolAddress(&pw2_, g_wq2);
  cudaGetSymbolAddress(&pw3_, g_wq3);
  float*  py  = (float*)py_;
  float*  ph1 = (float*)ph1_;
  float*  ph2 = (float*)ph2_;
  float4* pw1 = (float4*)pw1_;
  float4* pw2 = (float4*)pw2_;
  float4* pw3 = (float4*)pw3_;

  prepack_kernel<<<320, 256>>>(w1, w2, w3, wqk);
  ln_partial_kernel<<<dim3(NB, BB), 256>>>(x);
  ln_final_kernel<<<BB, 256>>>();
  prep_mma_kernel<<<(BF*NN)/64, 256, PREPM_SMEM>>>(x);
  attn_mma_kernel<<<dim3(9, BF), 128, ATTN_SMEM>>>(x);
  conv3_mma_kernel<<<dim3(12, 24, 2), 256, C3_SMEM>>>(py,  pw1, b1, ph1, 1);
  conv3_mma_kernel<<<dim3(12, 24, 2), 256, C3_SMEM>>>(ph1, pw2, b2, ph2, 1);
  conv1x1_mma_kernel<<<576, 256, C1M_SMEM>>>(ph2, pw3, b3, x, out);
}

// round 14
// speedup vs baseline: 1.1359x; 1.1359x over previous
#include <cuda_runtime.h>
#include <cuda_bf16.h>
#include <math.h>
#include <stdint.h>

#define BB 2
#define C 128
#define H 192
#define W 192
#define HW (H*W)
#define CHW (C*HW)
#define E 128
#define SWID 24
#define NN 576
#define BF 128
#define NB 256

// ---------------- mma helpers (base PTX, compute_103-safe) ----------------
__device__ __forceinline__ uint32_t s2u(const void* p){
  uint32_t a;
  asm("{ .reg .u64 t; cvta.to.shared.u64 t, %1; cvt.u32.u64 %0, t; }" : "=r"(a) : "l"(p));
  return a;
}
__device__ __forceinline__ void cp16(uint32_t d, const void* g){
  asm volatile("cp.async.cg.shared.global [%0], [%1], 16;" :: "r"(d), "l"(g));
}
#define CP_COMMIT() asm volatile("cp.async.commit_group;" ::: "memory")

__device__ __forceinline__ void ldsm4(uint32_t* r, uint32_t addr){
  asm volatile("ldmatrix.sync.aligned.m8n8.x4.shared.b16 {%0,%1,%2,%3}, [%4];"
    : "=r"(r[0]),"=r"(r[1]),"=r"(r[2]),"=r"(r[3]) : "r"(addr));
}
__device__ __forceinline__ void mma_bf16(float* c, const uint32_t* a, uint32_t b0, uint32_t b1){
  asm volatile("mma.sync.aligned.m16n8k16.row.col.f32.bf16.bf16.f32 "
    "{%0,%1,%2,%3}, {%4,%5,%6,%7}, {%8,%9}, {%0,%1,%2,%3};"
    : "+f"(c[0]),"+f"(c[1]),"+f"(c[2]),"+f"(c[3])
    : "r"(a[0]),"r"(a[1]),"r"(a[2]),"r"(a[3]), "r"(b0),"r"(b1));
}
__device__ __forceinline__ void mma_tf32(float* c, uint32_t a0, uint32_t a1, uint32_t a2,
                                         uint32_t a3, uint32_t b0, uint32_t b1){
  asm volatile("mma.sync.aligned.m16n8k8.row.col.f32.tf32.tf32.f32 "
    "{%0,%1,%2,%3}, {%4,%5,%6,%7}, {%8,%9}, {%0,%1,%2,%3};"
    : "+f"(c[0]),"+f"(c[1]),"+f"(c[2]),"+f"(c[3])
    : "r"(a0),"r"(a1),"r"(a2),"r"(a3), "r"(b0),"r"(b1));
}
__device__ __forceinline__ void mma_tf32_f4(float* cA, float* cB, uint32_t a0, uint32_t a1,
                                            uint32_t a2, uint32_t a3, float4 bv){
  mma_tf32(cA, a0, a1, a2, a3, __float_as_uint(bv.x), __float_as_uint(bv.y));
  mma_tf32(cB, a0, a1, a2, a3, __float_as_uint(bv.z), __float_as_uint(bv.w));
}
__device__ __forceinline__ uint32_t packbf(float lo, float hi){
  uint32_t d; asm("cvt.rn.bf16x2.f32 %0, %1, %2;" : "=r"(d) : "f"(hi), "f"(lo)); return d;
}
__device__ __forceinline__ float tf32r(float v){
  uint32_t o; asm("cvt.rna.tf32.f32 %0, %1;" : "=r"(o) : "f"(v));
  return __uint_as_float(o);
}
__device__ __forceinline__ uint32_t ldss(uint32_t a){
  uint32_t v; asm volatile("ld.shared.b32 %0, [%1];" : "=r"(v) : "r"(a)); return v;
}

// ---------------- scratch (static device globals; no allocation) ----------------
__device__ float g_part[BB*NB*2];
__device__ float g_mv[4];
__device__ __nv_bfloat16 g_qkh[(size_t)BF*NN*E];   // [bf][n][e] unit-norm rows
__device__ __nv_bfloat16 g_vh [(size_t)BF*NN*C];   // [bf][c][n]
__device__ float g_y [(size_t)BB*CHW];
__device__ float g_h1[(size_t)BB*CHW];
__device__ float g_h2[(size_t)BB*CHW];
__device__ float4 g_wq1[36864];   // conv1 [kk*16+ci8][jp][lane] paired n8 frags
__device__ float4 g_wq2[36864];   // conv2
__device__ float4 g_wq3[4096];    // 1x1  [ci8][jp][lane]
__device__ float4 g_wq4[4096];    // wqk  [k8*2+eh][jp][lane]

// ---------------- LayerNorm stats ----------------
__global__ void ln_partial_kernel(const float* __restrict__ x){
  int b = blockIdx.y;
  const float* xb = x + (size_t)b*CHW;
  float s = 0.f, ss = 0.f;
  for (int i = blockIdx.x*256 + threadIdx.x; i < CHW; i += NB*256){
    float v = xb[i]; s += v; ss += v*v;
  }
  #pragma unroll
  for (int o = 16; o; o >>= 1){
    s  += __shfl_xor_sync(0xffffffffu, s,  o);
    ss += __shfl_xor_sync(0xffffffffu, ss, o);
  }
  __shared__ float rs[8], rss[8];
  int warp = threadIdx.x >> 5, lane = threadIdx.x & 31;
  if (!lane){ rs[warp] = s; rss[warp] = ss; }
  __syncthreads();
  if (!threadIdx.x){
    float a = 0.f, c2 = 0.f;
    #pragma unroll
    for (int i = 0; i < 8; i++){ a += rs[i]; c2 += rss[i]; }
    g_part[(b*NB + blockIdx.x)*2]   = a;
    g_part[(b*NB + blockIdx.x)*2+1] = c2;
  }
}

__global__ void ln_final_kernel(){
  int b = blockIdx.x, t = threadIdx.x;
  float s  = g_part[(b*NB + t)*2];
  float ss = g_part[(b*NB + t)*2+1];
  #pragma unroll
  for (int o = 16; o; o >>= 1){
    s  += __shfl_xor_sync(0xffffffffu, s,  o);
    ss += __shfl_xor_sync(0xffffffffu, ss, o);
  }
  __shared__ float rs[8], rss[8];
  int warp = t >> 5, lane = t & 31;
  if (!lane){ rs[warp] = s; rss[warp] = ss; }
  __syncthreads();
  if (!t){
    float a = 0.f, c2 = 0.f;
    #pragma unroll
    for (int i = 0; i < 8; i++){ a += rs[i]; c2 += rss[i]; }
    float mean = a / (float)CHW;
    float var  = c2 / (float)CHW - mean*mean;
    g_mv[b*2]   = mean;
    g_mv[b*2+1] = rsqrtf(var + 1e-5f);
  }
}

// ---------------- weight prepack: paired-fragment float4, tf32-rounded ----------------
__global__ void prepack_kernel(const float* __restrict__ w1, const float* __restrict__ w2,
                               const float* __restrict__ w3, const float* __restrict__ wqk){
  int i = blockIdx.x*256 + threadIdx.x;
  if (i < 2*36864){
    const float* w = (i < 36864) ? w1 : w2;
    float4* dst = (i < 36864) ? g_wq1 : g_wq2;
    int j = (i < 36864) ? i : i - 36864;
    int lane = j & 31, jp = (j >> 5) & 7, kidx = j >> 8;
    int kk = kidx >> 4, ci8 = kidx & 15;
    int t = lane & 3, g = lane >> 2;
    int ci = ci8*8 + t;
    int coA = (2*jp)*8 + g, coB = (2*jp+1)*8 + g;
    dst[j] = make_float4(tf32r(w[(coA*128 + ci)*9 + kk]),
                         tf32r(w[(coA*128 + ci + 4)*9 + kk]),
                         tf32r(w[(coB*128 + ci)*9 + kk]),
                         tf32r(w[(coB*128 + ci + 4)*9 + kk]));
  } else if (i < 2*36864 + 4096){
    int j = i - 2*36864;
    int lane = j & 31, jp = (j >> 5) & 7, ci8 = j >> 8;
    int t = lane & 3, g = lane >> 2;
    int coA = (2*jp)*8 + g, coB = (2*jp+1)*8 + g;
    g_wq3[j] = make_float4(tf32r(w3[coA*128 + ci8*8 + t]),
                           tf32r(w3[coA*128 + ci8*8 + t + 4]),
                           tf32r(w3[coB*128 + ci8*8 + t]),
                           tf32r(w3[coB*128 + ci8*8 + t + 4]));
  } else {
    int j = i - 2*36864 - 4096;
    if (j < 4096){
      int lane = j & 31, jp = (j >> 5) & 3, e2 = (j >> 7) & 1, k8 = j >> 8;
      int t = lane & 3, g = lane >> 2;
      int n8a = e2*8 + 2*jp, n8b = n8a + 1;
      g_wq4[j] = make_float4(tf32r(wqk[(k8*8 + t)*E     + n8a*8 + g]),
                             tf32r(wqk[(k8*8 + t + 4)*E + n8a*8 + g]),
                             tf32r(wqk[(k8*8 + t)*E     + n8b*8 + g]),
                             tf32r(wqk[(k8*8 + t + 4)*E + n8b*8 + g]));
    }
  }
}

// ---------------- prep: unshuffle + tf32-mma qk projection + row L2-norm ----------------
#define PREPM_SMEM (36864 + 512)
__global__ __launch_bounds__(256) void prep_mma_kernel(const float* __restrict__ x){
  int blk = blockIdx.x;
  int r0  = blk*64;
  int bf  = r0 / NN;
  int b   = bf >> 6, k = bf & 63, dy = k >> 3, dx = k & 7;
  float mean = g_mv[b*2], rstd = g_mv[b*2+1];
  extern __shared__ float sm[];
  float* xs  = sm;                 // [c][72]
  float* ssq = sm + 9216;          // [64][2]
  int tid = threadIdx.x;
  int lane = tid & 31, wm = tid >> 5;
  int t = lane & 3, g = lane >> 2;
  uint32_t sb = s2u(sm);

  int n0 = r0 - bf*NN;
  for (int l = tid; l < 8192; l += 256){
    int c = l >> 6, i = l & 63;
    int n  = n0 + i;
    int sh = n / SWID, swp = n - sh*SWID;
    int h  = sh*8 + dy, w = swp*8 + dx;
    float xv = x[(size_t)(b*C + c)*HW + h*W + w];
    g_vh[((size_t)bf*C + c)*NN + n] = __float2bfloat16(xv);
    xs[c*72 + i] = tf32r((xv - mean)*rstd);
  }
  __syncthreads();

  int rg = wm & 3, eh = wm >> 2;
  float acc[8][4] = {};
  #pragma unroll
  for (int k8 = 0; k8 < 16; k8++){
    uint32_t ab = sb + (uint32_t)(((k8*8 + t)*72 + rg*16 + g)*4);
    uint32_t a0 = ldss(ab);
    uint32_t a1 = ldss(ab + 32);
    uint32_t a2 = ldss(ab + 4*72*4);
    uint32_t a3 = ldss(ab + 4*72*4 + 32);
    const float4* wrow = g_wq4 + (size_t)((k8*2 + eh)*4)*32 + lane;
    #pragma unroll
    for (int jp = 0; jp < 4; jp++){
      float4 bv = __ldg(wrow + jp*32);
      mma_tf32_f4(acc[2*jp], acc[2*jp+1], a0, a1, a2, a3, bv);
    }
  }

  float s0 = 0.f, s1 = 0.f;
  #pragma unroll
  for (int j = 0; j < 8; j++){
    s0 += acc[j][0]*acc[j][0] + acc[j][1]*acc[j][1];
    s1 += acc[j][2]*acc[j][2] + acc[j][3]*acc[j][3];
  }
  s0 += __shfl_xor_sync(0xffffffffu, s0, 1);
  s0 += __shfl_xor_sync(0xffffffffu, s0, 2);
  s1 += __shfl_xor_sync(0xffffffffu, s1, 1);
  s1 += __shfl_xor_sync(0xffffffffu, s1, 2);
  if (t == 0){
    ssq[(rg*16 + g)*2 + eh]     = s0;
    ssq[(rg*16 + g + 8)*2 + eh] = s1;
  }
  __syncthreads();
  int row0 = rg*16 + g, row1 = row0 + 8;
  float inv0 = 1.f/(sqrtf(ssq[row0*2] + ssq[row0*2+1]) + 1e-8f);
  float inv1 = 1.f/(sqrtf(ssq[row1*2] + ssq[row1*2+1]) + 1e-8f);

  __nv_bfloat16* q0 = g_qkh + (size_t)(r0 + row0)*E + eh*64 + 2*t;
  __nv_bfloat16* q1 = g_qkh + (size_t)(r0 + row1)*E + eh*64 + 2*t;
  #pragma unroll
  for (int j = 0; j < 8; j++){
    *(uint32_t*)(q0 + j*8) = packbf(acc[j][0]*inv0, acc[j][1]*inv0);
    *(uint32_t*)(q1 + j*8) = packbf(acc[j][2]*inv1, acc[j][3]*inv1);
  }
}

// ---------------- attention: mma.sync bf16 flash, single-V-buffer ----------------
#define AOFF_Q  0
#define AOFF_K0 16384
#define AOFF_K1 32768
#define AOFF_V  49152
#define ATTN_SMEM 65536

__device__ __forceinline__ void load_k(uint32_t sb, const __nv_bfloat16* qsrc, int jt, int tid){
  uint32_t kb = sb + ((jt & 1) ? AOFF_K1 : AOFF_K0);
  const __nv_bfloat16* ks = qsrc + (size_t)jt*64*E;
  #pragma unroll
  for (int r = 0; r < 8; r++){
    int idx = tid + 128*r;
    int row = idx >> 4, ch = idx & 15;
    cp16(kb + row*256 + ((ch ^ (row & 7))*16), ks + (size_t)row*E + ch*8);
  }
  CP_COMMIT();
}
__device__ __forceinline__ void load_v(uint32_t sb, const __nv_bfloat16* vsrc, int jt, int tid){
  uint32_t vb = sb + AOFF_V;
  const __nv_bfloat16* vs = vsrc + jt*64;
  #pragma unroll
  for (int r = 0; r < 8; r++){
    int idx = tid + 128*r;
    int row = idx >> 3, ch = idx & 7;
    cp16(vb + row*128 + ((ch ^ (row & 7))*16), vs + (size_t)row*NN + ch*8);
  }
  CP_COMMIT();
}

__global__ __launch_bounds__(128) void attn_mma_kernel(const float* __restrict__ x){
  extern __shared__ char smc[];
  const int tid = threadIdx.x;
  const int lane = tid & 31, w = tid >> 5;
  const int rt = blockIdx.x, bf = blockIdx.y;
  const int r0 = rt*64;
  const __nv_bfloat16* qsrc = g_qkh + (size_t)bf*NN*E;
  const __nv_bfloat16* vsrc = g_vh  + (size_t)bf*C*NN;
  uint32_t sb = s2u(smc);

  {
    const __nv_bfloat16* qs = qsrc + (size_t)r0*E;
    #pragma unroll
    for (int r = 0; r < 8; r++){
      int idx = tid + 128*r;
      int row = idx >> 4, ch = idx & 15;
      cp16(sb + AOFF_Q + row*256 + ((ch ^ (row & 7))*16), qs + (size_t)row*E + ch*8);
    }
    CP_COMMIT();
  }
  load_k(sb, qsrc, 0, tid);
  asm volatile("cp.async.wait_group 0;" ::: "memory");
  __syncthreads();

  uint32_t qa[8][4];
  #pragma unroll
  for (int kk = 0; kk < 8; kk++){
    int row = w*16 + (lane & 15);
    int ch  = kk*2 + (lane >> 4);
    ldsm4(qa[kk], sb + AOFF_Q + row*256 + ((ch ^ (row & 7))*16));
  }

  float oacc[16][4];
  #pragma unroll
  for (int i = 0; i < 16; i++){ oacc[i][0]=0.f; oacc[i][1]=0.f; oacc[i][2]=0.f; oacc[i][3]=0.f; }
  float rsum0 = 0.f, rsum1 = 0.f;
  const float invsE = 0.08838834764831845f;

  for (int jt = 0; jt < 9; jt++){
    __syncthreads();
    if (jt < 8) load_k(sb, qsrc, jt+1, tid);
    load_v(sb, vsrc, jt, tid);
    if (jt < 8) asm volatile("cp.async.wait_group 2;" ::: "memory");
    else        asm volatile("cp.async.wait_group 1;" ::: "memory");
    __syncthreads();

    uint32_t kbase = sb + ((jt & 1) ? AOFF_K1 : AOFF_K0);

    float sc[8][4];
    #pragma unroll
    for (int i = 0; i < 8; i++){ sc[i][0]=0.f; sc[i][1]=0.f; sc[i][2]=0.f; sc[i][3]=0.f; }
    #pragma unroll
    for (int jp = 0; jp < 4; jp++){
      #pragma unroll
      for (int kk = 0; kk < 8; kk++){
        uint32_t kb[4];
        int row = jp*16 + (lane & 15);
        int ch  = kk*2 + (lane >> 4);
        ldsm4(kb, kbase + row*256 + ((ch ^ (row & 7))*16));
        mma_bf16(sc[2*jp],   qa[kk], kb[0], kb[2]);
        mma_bf16(sc[2*jp+1], qa[kk], kb[1], kb[3]);
      }
    }

    if (jt < 8) asm volatile("cp.async.wait_group 1;" ::: "memory");
    else        asm volatile("cp.async.wait_group 0;" ::: "memory");
    __syncthreads();

    uint32_t pa[4][4];
    #pragma unroll
    for (int j = 0; j < 8; j++){
      float p0 = __expf(sc[j][0]*invsE), p1 = __expf(sc[j][1]*invsE);
      float p2 = __expf(sc[j][2]*invsE), p3 = __expf(sc[j][3]*invsE);
      rsum0 += p0 + p1; rsum1 += p2 + p3;
      int kk = j >> 1;
      if ((j & 1) == 0){ pa[kk][0] = packbf(p0,p1); pa[kk][1] = packbf(p2,p3); }
      else             { pa[kk][2] = packbf(p0,p1); pa[kk][3] = packbf(p2,p3); }
    }

    #pragma unroll
    for (int jnp = 0; jnp < 8; jnp++){
      #pragma unroll
      for (int kk = 0; kk < 4; kk++){
        uint32_t vb[4];
        int row = jnp*16 + (lane & 15);
        int ch  = kk*2 + (lane >> 4);
        ldsm4(vb, sb + AOFF_V + row*128 + ((ch ^ (row & 7))*16));
        mma_bf16(oacc[2*jnp],   pa[kk], vb[0], vb[2]);
        mma_bf16(oacc[2*jnp+1], pa[kk], vb[1], vb[3]);
      }
    }
  }

  rsum0 += __shfl_xor_sync(0xffffffffu, rsum0, 1);
  rsum0 += __shfl_xor_sync(0xffffffffu, rsum0, 2);
  rsum1 += __shfl_xor_sync(0xffffffffu, rsum1, 1);
  rsum1 += __shfl_xor_sync(0xffffffffu, rsum1, 2);
  float inv0 = 1.f/rsum0, inv1 = 1.f/rsum1;

  int g = lane >> 2, t4 = lane & 3;
  int b = bf >> 6, kk2 = bf & 63, dy = kk2 >> 3, dx = kk2 & 7;
  int nA = r0 + w*16 + g;
  int nB = nA + 8;
  int shA = nA / SWID, swA = nA - shA*SWID;
  int shB = nB / SWID, swB = nB - shB*SWID;
  size_t baseA = (size_t)b*CHW + (size_t)(shA*8 + dy)*W + (swA*8 + dx);
  size_t baseB = (size_t)b*CHW + (size_t)(shB*8 + dy)*W + (swB*8 + dx);
  #pragma unroll
  for (int jn = 0; jn < 16; jn++){
    int c0 = jn*8 + 2*t4;
    size_t giA = baseA + (size_t)c0*HW;
    size_t giB = baseB + (size_t)c0*HW;
    g_y[giA]    = x[giA]    + oacc[jn][0]*inv0;
    g_y[giA+HW] = x[giA+HW] + oacc[jn][1]*inv0;
    g_y[giB]    = x[giB]    + oacc[jn][2]*inv1;
    g_y[giB+HW] = x[giB+HW] + oacc[jn][3]*inv1;
  }
}

// ---------------- 3x3 dilated conv via tf32 mma implicit GEMM, cog-split (64 co/block) ----------------
#define C3_SMEM (7936*4)
__global__ __launch_bounds__(256,3) void conv3_mma_kernel(const float* __restrict__ in,
                                                          const float4* __restrict__ wp,
                                                          const float* __restrict__ bias,
                                                          float* __restrict__ out){
  int txle = blockIdx.x*16, tyle = blockIdx.y*8;
  int z = blockIdx.z; int b = z >> 1, cog = z & 1;
  extern __shared__ float sm[];
  int tid = threadIdx.x, lane = tid & 31, wm = tid >> 5;
  int t = lane & 3, g = lane >> 2;
  uint32_t sb = s2u(sm);
  float acc[8][4] = {};

  for (int chunk = 0; chunk < 4; chunk++){
    __syncthreads();
    for (int l = tid; l < 7680; l += 256){
      int ci = l / 240, r = l - ci*240, yy = r / 20, xx = r - yy*20;
      int gy = tyle + yy - 2, gx = txle + xx - 2;
      float v = 0.f;
      if (gy >= 0 && gy < H && gx >= 0 && gx < W)
        v = in[(size_t)(b*C + chunk*32 + ci)*HW + gy*W + gx];
      sm[ci*248 + yy*20 + xx] = tf32r(v);
    }
    __syncthreads();
    #pragma unroll
    for (int kk = 0; kk < 9; kk++){
      int ky = kk/3, kx = kk - ky*3;
      #pragma unroll
      for (int c8 = 0; c8 < 4; c8++){
        uint32_t ab = sb + (uint32_t)(((c8*8 + t)*248 + (wm + 2*ky)*20 + g + 2*kx)*4);
        uint32_t a0 = ldss(ab);
        uint32_t a1 = ldss(ab + 32);
        uint32_t a2 = ldss(ab + 4*248*4);
        uint32_t a3 = ldss(ab + 4*248*4 + 32);
        const float4* wrow = wp + (size_t)((kk*16 + chunk*4 + c8)*8 + cog*4)*32 + lane;
        #pragma unroll
        for (int jp = 0; jp < 4; jp++){
          float4 bv = __ldg(wrow + jp*32);
          mma_tf32_f4(acc[2*jp], acc[2*jp+1], a0, a1, a2, a3, bv);
        }
      }
    }
  }

  int gx0 = txle + g, gy = tyle + wm;
  #pragma unroll
  for (int j = 0; j < 8; j++){
    int co = cog*64 + j*8 + 2*t;
    float2 bb = *(const float2*)&bias[co];
    size_t o0 = (size_t)(b*C + co)*HW + (size_t)gy*W + gx0;
    out[o0]        = fmaxf(acc[j][0] + bb.x, 0.f);
    out[o0 + HW]   = fmaxf(acc[j][1] + bb.y, 0.f);
    out[o0 + 8]    = fmaxf(acc[j][2] + bb.x, 0.f);
    out[o0 + HW+8] = fmaxf(acc[j][3] + bb.y, 0.f);
  }
}

// ---------------- 1x1 conv via tf32 mma + bias + residual ----------------
#define C1M_SMEM (32*136*4)
__global__ __launch_bounds__(256) void conv1x1_mma_kernel(const float* __restrict__ hin,
                                                          const float4* __restrict__ wp,
                                                          const float* __restrict__ bias,
                                                          const float* __restrict__ x,
                                                          float* __restrict__ out){
  int blk = blockIdx.x;
  int b = blk / 288, hw0 = (blk - b*288)*128;
  extern __shared__ float sm[];
  int tid = threadIdx.x, lane = tid & 31, wm = tid >> 5;
  int t = lane & 3, g = lane >> 2;
  uint32_t sb = s2u(sm);
  float acc[16][4] = {};

  for (int chunk = 0; chunk < 4; chunk++){
    __syncthreads();
    for (int l = tid; l < 4096; l += 256){
      int ci = l >> 7, p = l & 127;
      sm[ci*136 + p] = tf32r(hin[(size_t)(b*C + chunk*32 + ci)*HW + hw0 + p]);
    }
    __syncthreads();
    #pragma unroll
    for (int c8 = 0; c8 < 4; c8++){
      uint32_t ab = sb + (uint32_t)(((c8*8 + t)*136 + wm*16 + g)*4);
      uint32_t a0 = ldss(ab);
      uint32_t a1 = ldss(ab + 32);
      uint32_t a2 = ldss(ab + 4*136*4);
      uint32_t a3 = ldss(ab + 4*136*4 + 32);
      const float4* wrow = wp + (size_t)((chunk*4 + c8)*8)*32 + lane;
      #pragma unroll
      for (int jp = 0; jp < 8; jp++){
        float4 bv = __ldg(wrow + jp*32);
        mma_tf32_f4(acc[2*jp], acc[2*jp+1], a0, a1, a2, a3, bv);
      }
    }
  }

  int p0 = hw0 + wm*16 + g;
  #pragma unroll
  for (int j = 0; j < 16; j++){
    int co = j*8 + 2*t;
    float2 bb = *(const float2*)&bias[co];
    size_t o0 = (size_t)(b*C + co)*HW + p0;
    out[o0]        = x[o0]        + acc[j][0] + bb.x;
    out[o0 + HW]   = x[o0 + HW]   + acc[j][1] + bb.y;
    out[o0 + 8]    = x[o0 + 8]    + acc[j][2] + bb.x;
    out[o0 + HW+8] = x[o0 + HW+8] + acc[j][3] + bb.y;
  }
}

// ---------------- launch ----------------
extern "C" void kernel_launch(void* const* d_in, const int* in_sizes, int n_in,
                              void* d_out, int out_size){
  const float* x   = (const float*)d_in[0];
  const float* wqk = (const float*)d_in[1];
  const float* w1  = (const float*)d_in[2];
  const float* b1  = (const float*)d_in[3];
  const float* w2  = (const float*)d_in[4];
  const float* b2  = (const float*)d_in[5];
  const float* w3  = (const float*)d_in[6];
  const float* b3  = (const float*)d_in[7];
  float* out = (float*)d_out;

  cudaFuncSetAttribute(prep_mma_kernel,   cudaFuncAttributeMaxDynamicSharedMemorySize, PREPM_SMEM);
  cudaFuncSetAttribute(attn_mma_kernel,   cudaFuncAttributeMaxDynamicSharedMemorySize, ATTN_SMEM);
  cudaFuncSetAttribute(conv3_mma_kernel,  cudaFuncAttributeMaxDynamicSharedMemorySize, C3_SMEM);
  cudaFuncSetAttribute(conv1x1_mma_kernel,cudaFuncAttributeMaxDynamicSharedMemorySize, C1M_SMEM);

  void *py_, *ph1_, *ph2_, *pw1_, *pw2_, *pw3_;
  cudaGetSymbolAddress(&py_,  g_y);
  cudaGetSymbolAddress(&ph1_, g_h1);
  cudaGetSymbolAddress(&ph2_, g_h2);
  cudaGetSymbolAddress(&pw1_, g_wq1);
  cudaGetSymbolAddress(&pw2_, g_wq2);
  cudaGetSymbolAddress(&pw3_, g_wq3);
  float*  py  = (float*)py_;
  float*  ph1 = (float*)ph1_;
  float*  ph2 = (float*)ph2_;
  float4* pw1 = (float4*)pw1_;
  float4* pw2 = (float4*)pw2_;
  float4* pw3 = (float4*)pw3_;

  prepack_kernel<<<320, 256>>>(w1, w2, w3, wqk);
  ln_partial_kernel<<<dim3(NB, BB), 256>>>(x);
  ln_final_kernel<<<BB, 256>>>();
  prep_mma_kernel<<<(BF*NN)/64, 256, PREPM_SMEM>>>(x);
  attn_mma_kernel<<<dim3(9, BF), 128, ATTN_SMEM>>>(x);
  conv3_mma_kernel<<<dim3(12, 24, 4), 256, C3_SMEM>>>(py,  pw1, b1, ph1);
  conv3_mma_kernel<<<dim3(12, 24, 4), 256, C3_SMEM>>>(ph1, pw2, b2, ph2);
  conv1x1_mma_kernel<<<576, 256, C1M_SMEM>>>(ph2, pw3, b3, x, out);
}